// round 17
// baseline (speedup 1.0000x reference)
#include <cuda_runtime.h>

// Lyapunov spectrum for the Lorenz-Jacobian + row Gram-Schmidt reference.
//
// KEY IDENTITY: the reference's Q_t is row-orthonormal after every GS step,
// so the Gram matrix of M = (I+DT*J)Q_{t-1} is
//     S = M M^T = A (Q Q^T) A^T = A A^T,  A = I + DT*J(x,y,z),
// a pure function of the input sample (x,y,z). Outputs depend on S only ->
// elementwise map over (T, B) + sum over T. Q never materializes.
//
// R15: 39.7 us. R16: 37.6 us -- reduce kernel now pure fixed cost (5.4 us
// for 2 MB at 391 GB/s: launch ramp + latency, not BW). R17: FUSE the
// reduce into pass 1 via the last-block-arrival pattern (threadfence +
// per-column-group atomic counter; 32nd arriver sums its 64 columns in
// fixed order and writes out, then resets the counter for graph replays).
// Eliminates the ~5 us second launch; adds ~1 us overlapped tail.

#define T_STEPS 2048
#define BATCH   8192
#define ROWS4   (BATCH / 4)           // 2048 float4 per component row
#define G_CHUNK 32
#define CHUNK_T (T_STEPS / G_CHUNK)   // 64 steps per chunk
#define CTILE   32                    // column tiles (grid.x), 64 cols each

#define DTf     0.01f
#define S11c    0.98010004f          // 0.99^2
#define S22c    0.94737780f          // A22^2
#define S12c    0.016666668f         // 0.99 - A22
#define T01ac   0.99388373f          // 0.9/sqrt(0.82)
#define T01bc   0.10932722f          // 0.099/sqrt(0.82)
#define T02ac   0.11043153f          // 0.1/sqrt(0.82)
#define LAM0c  -9.9225469f           // 0.5*ln(0.82)/DT

__device__ float4 g_partials[G_CHUNK * 2 * ROWS4];   // 2 MB scratch
__device__ int    g_counters[CTILE];                 // zero-init; self-reset

__device__ __forceinline__ float frcp_approx(float v) {
    float r;
    asm("rcp.approx.f32 %0, %1;" : "=f"(r) : "f"(v));
    return r;
}

// squared GS residual norms (u11, v22) of one input sample
__device__ __forceinline__ void norms_from_sample(float x, float y, float z,
                                                  float &u11, float &v22)
{
    float c1 = fmaf(-DTf, z, 0.28f);       // DT*(28 - z)
    float cx = DTf * x;
    float cy = DTf * y;

    float cxsq = cx * cx;
    float s11  = fmaf(c1, c1, S11c + cxsq);
    float s12  = fmaf(c1, cy, S12c * cx);
    float s22  = fmaf(cy, cy, S22c + cxsq);

    // t0k = (q0' . m_k) with 1/sqrt(0.82) folded into the constants
    float t01 = fmaf(c1, T01ac, T01bc);
    float t02 = fmaf(cy, T01ac, T02ac * cx);

    u11 = fmaf(-t01, t01, s11);
    float u12 = fmaf(-t01, t02, s12);
    float u22 = fmaf(-t02, t02, s22);
    float w1  = frcp_approx(u11);
    v22 = fmaf(-u12 * u12, w1, u22);
}

// one time-step for 4 batch lanes
__device__ __forceinline__ void step4(const float4 &x, const float4 &y,
                                      const float4 &z,
                                      float4 &pl1, float4 &pl2)
{
    float u, v;
    norms_from_sample(x.x, y.x, z.x, u, v); pl1.x *= u; pl2.x *= v;
    norms_from_sample(x.y, y.y, z.y, u, v); pl1.y *= u; pl2.y *= v;
    norms_from_sample(x.z, y.z, z.z, u, v); pl1.z *= u; pl2.z *= v;
    norms_from_sample(x.w, y.w, z.w, u, v); pl1.w *= u; pl2.w *= v;
}

#define LOAD_GROUP(bx, by, bz, g)                                              \
    _Pragma("unroll")                                                          \
    for (int i = 0; i < 4; i++) {                                              \
        const float4* q = p + (size_t)((g) * 4 + i) * 3 * ROWS4;               \
        bx[i] = __ldcs(q);                                                     \
        by[i] = __ldcs(q + ROWS4);                                             \
        bz[i] = __ldcs(q + 2 * ROWS4);                                         \
    }

// 64-thread blocks, 7 blocks/SM: 1024 blocks ~= one full wave.
__global__ __launch_bounds__(64, 7)
void lya_fused_kernel(const float4* __restrict__ traj4,
                      float4* __restrict__ out4)
{
    const int tb    = blockIdx.x * 64 + threadIdx.x;    // 0 .. ROWS4-1
    const int chunk = blockIdx.y;
    const float4* p = traj4 + (size_t)chunk * CHUNK_T * 3 * ROWS4 + tb;

    float4 l1 = make_float4(0.f, 0.f, 0.f, 0.f);
    float4 l2 = make_float4(0.f, 0.f, 0.f, 0.f);

    float4 xa[4], ya[4], za[4], xb[4], yb[4], zb[4];
    const int NG = CHUNK_T / 4;                         // 16 groups of 4 steps

    LOAD_GROUP(xa, ya, za, 0)

    // steady state: branch-clean, double-buffered
#pragma unroll 1
    for (int g = 0; g < NG - 2; g += 2) {
        float4 pl1 = make_float4(1.f, 1.f, 1.f, 1.f);
        float4 pl2 = make_float4(1.f, 1.f, 1.f, 1.f);

        LOAD_GROUP(xb, yb, zb, g + 1)
#pragma unroll
        for (int i = 0; i < 4; i++) step4(xa[i], ya[i], za[i], pl1, pl2);

        LOAD_GROUP(xa, ya, za, g + 2)
#pragma unroll
        for (int i = 0; i < 4; i++) step4(xb[i], yb[i], zb[i], pl1, pl2);

        // one log per 8 steps per lane (product range ~[0.3, 1.5]^8, safe)
        l1.x += __log2f(pl1.x); l1.y += __log2f(pl1.y);
        l1.z += __log2f(pl1.z); l1.w += __log2f(pl1.w);
        l2.x += __log2f(pl2.x); l2.y += __log2f(pl2.y);
        l2.z += __log2f(pl2.z); l2.w += __log2f(pl2.w);
    }

    // epilogue: last two groups
    {
        float4 pl1 = make_float4(1.f, 1.f, 1.f, 1.f);
        float4 pl2 = make_float4(1.f, 1.f, 1.f, 1.f);

        LOAD_GROUP(xb, yb, zb, NG - 1)
#pragma unroll
        for (int i = 0; i < 4; i++) step4(xa[i], ya[i], za[i], pl1, pl2);
#pragma unroll
        for (int i = 0; i < 4; i++) step4(xb[i], yb[i], zb[i], pl1, pl2);

        l1.x += __log2f(pl1.x); l1.y += __log2f(pl1.y);
        l1.z += __log2f(pl1.z); l1.w += __log2f(pl1.w);
        l2.x += __log2f(pl2.x); l2.y += __log2f(pl2.y);
        l2.z += __log2f(pl2.z); l2.w += __log2f(pl2.w);
    }

    g_partials[(chunk * 2 + 0) * ROWS4 + tb] = l1;
    g_partials[(chunk * 2 + 1) * ROWS4 + tb] = l2;

    // ---- last-block-arrival fused reduce (threadFenceReduction pattern) ----
    __shared__ int sh_last;
    __threadfence();                       // partials visible chip-wide
    __syncthreads();                       // all 64 threads' stores issued
    if (threadIdx.x == 0) {
        int old = atomicAdd(&g_counters[blockIdx.x], 1);
        sh_last = (old == G_CHUNK - 1);
    }
    __syncthreads();

    if (sh_last) {
        __threadfence();                   // acquire all groups' partials
        float4 s1 = make_float4(0.f, 0.f, 0.f, 0.f);
        float4 s2 = make_float4(0.f, 0.f, 0.f, 0.f);
        // fixed-order sum over all 32 chunks for this thread's column
#pragma unroll 4
        for (int g = 0; g < G_CHUNK; g++) {
            float4 a = g_partials[(g * 2 + 0) * ROWS4 + tb];
            float4 b = g_partials[(g * 2 + 1) * ROWS4 + tb];
            s1.x += a.x; s1.y += a.y; s1.z += a.z; s1.w += a.w;
            s2.x += b.x; s2.y += b.y; s2.z += b.z; s2.w += b.w;
        }
        // l = sum(log2 n^2) -> lambda = l * 0.5*ln2/(T*DT)
        const float scale = 0.5f * 0.69314718055994531f / (2048.0f * 0.01f);
        out4[tb] = make_float4(LAM0c, LAM0c, LAM0c, LAM0c);
        out4[ROWS4 + tb] = make_float4(s1.x * scale, s1.y * scale,
                                       s1.z * scale, s1.w * scale);
        out4[2 * ROWS4 + tb] = make_float4(s2.x * scale, s2.y * scale,
                                           s2.z * scale, s2.w * scale);
        if (threadIdx.x == 0)
            g_counters[blockIdx.x] = 0;    // reset for next graph replay
    }
}

extern "C" void kernel_launch(void* const* d_in, const int* in_sizes, int n_in,
                              void* d_out, int out_size)
{
    const float4* traj4 = (const float4*)d_in[0];
    float4* out4 = (float4*)d_out;
    (void)in_sizes; (void)n_in; (void)out_size;

    lya_fused_kernel<<<dim3(CTILE, G_CHUNK), 64>>>(traj4, out4);
}